// round 16
// baseline (speedup 1.0000x reference)
#include <cuda_runtime.h>
#include <cuda_bf16.h>
#include <math.h>
#include <stdint.h>

// Problem constants
#define Bq 64
#define Tq 512
#define Iq 512
#define Hq 1024
#define Gq 4096      // 4*H
#define Cq 20
#define MTOT (Bq*Tq) // 32768
#define NBLK 128     // persistent blocks (<148 => all co-resident)

// sgemm_bf16 smem (uint32 words): 3-stage Xs[3][128][20] + Ws[3][128][20]
#define GRS 20
#define GEMM_SMEM_WORDS (3*128*GRS + 3*128*GRS)
#define GEMM_SMEM_BYTES (GEMM_SMEM_WORDS * 4)    // 61440

// lstm_layer smem layout (uint32 words)
#define WSTR 516
#define HCH  260
#define HCHBUF (64*HCH)           // 16640 words
#define WOFF2 0
#define HOFF2 (32*WSTR)           // 16512
#define ROFF2 (HOFF2 + 2*HCHBUF)  // 49792
#define LSTM_SMEM_WORDS (ROFF2 + 2*64*36)
#define LSTM_SMEM_BYTES (LSTM_SMEM_WORDS * 4)    // 217600

// ---- scratch (static device allocations; no cudaMalloc allowed) ----
__device__ float g_xproj[(size_t)MTOT * Gq];   // 512 MB, reused by both layers
__device__ __nv_bfloat16 g_hs2b[(size_t)MTOT * Hq];  // 67 MB bf16 layer-2 hseq
__device__ __nv_bfloat16 g_xb[(size_t)MTOT * Hq];    // 64 MB bf16
__device__ __nv_bfloat16 g_wb[(size_t)Gq * Hq];      // 8 MB bf16 weights
__device__ __nv_bfloat16 g_hbufb[2][Bq * Hq];  // h ping-pong (bf16)
__device__ float g_emis[(size_t)MTOT * Cq];    // (T,B,C)
__device__ float g_llh[Bq];
__device__ unsigned g_flags[NBLK * 32];        // distributed barrier flags (128B apart)

__device__ __forceinline__ void cp_async16(void* smem_dst, const void* gmem_src)
{
    uint32_t s = (uint32_t)__cvta_generic_to_shared(smem_dst);
    asm volatile("cp.async.cg.shared.global [%0], [%1], 16;\n" :: "r"(s), "l"(gmem_src));
}
__device__ __forceinline__ void cp_commit()
{
    asm volatile("cp.async.commit_group;\n");
}
__device__ __forceinline__ void cp_wait0()
{
    asm volatile("cp.async.wait_group 0;\n");
}
__device__ __forceinline__ void cp_wait1()
{
    asm volatile("cp.async.wait_group 1;\n");
}

// bf16 MMA: D(16x8,f32) += A(16x16,row,bf16) * B(16x8,col,bf16)
__device__ __forceinline__ void mma_bf16(float* d, const uint32_t* a, const uint32_t* b)
{
    asm volatile(
        "mma.sync.aligned.m16n8k16.row.col.f32.bf16.bf16.f32 "
        "{%0,%1,%2,%3}, {%4,%5,%6,%7}, {%8,%9}, {%0,%1,%2,%3};"
        : "+f"(d[0]), "+f"(d[1]), "+f"(d[2]), "+f"(d[3])
        : "r"(a[0]), "r"(a[1]), "r"(a[2]), "r"(a[3]), "r"(b[0]), "r"(b[1]));
}

// ============================================================
// Elementwise fp32 -> bf16.
// ============================================================
__global__ void cvt_bf16(const float* __restrict__ src, __nv_bfloat16* __restrict__ dst,
                         int nquads)
{
    int i = blockIdx.x * blockDim.x + threadIdx.x;
    if (i >= nquads) return;
    float4 v = *(const float4*)(src + (size_t)i * 4);
    __nv_bfloat162 p0 = __floats2bfloat162_rn(v.x, v.y);
    __nv_bfloat162 p1 = __floats2bfloat162_rn(v.z, v.w);
    uint2 o;
    o.x = *(const uint32_t*)&p0;
    o.y = *(const uint32_t*)&p1;
    *(uint2*)(dst + (size_t)i * 4) = o;
}

// ============================================================
// bf16 tensor-core GEMM: Y = X(MxK)*W(NxK)^T + bias (fp32 out)
// Block tile 128m x 128n, BK=32, 256 threads (8 warps),
// warp tile 32m x 64n, m16n8k16, 3-stage cp.async pipeline
// (wait_group 1), 2 CTAs/SM. (R13 proven configuration.)
// If remap!=0, X row m = b*T+t and output row becomes t*B+b.
// ============================================================
__global__ void __launch_bounds__(256, 2)
sgemm_bf16(const __nv_bfloat16* __restrict__ X, const __nv_bfloat16* __restrict__ W,
           const float* __restrict__ bias, float* __restrict__ Y,
           int K, int remap)
{
    extern __shared__ uint32_t gsm[];
    uint32_t* Xs = gsm;                 // [3][128][GRS]
    uint32_t* Ws = gsm + 3 * 128 * GRS; // [3][128][GRS]

    const int bn = blockIdx.x * 128;
    const int bm = blockIdx.y * 128;
    const int tid = threadIdx.x;
    const int warp = tid >> 5;
    const int lane = tid & 31;
    const int gid = lane >> 2;
    const int tg  = lane & 3;
    const int wm = warp >> 1;        // 0..3 -> m0 = wm*32
    const int wn = warp & 1;         // 0..1 -> n0 = wn*64

    float acc[2][8][4] = {};
    const int nb = K >> 5;

    // prefetch tiles 0 and 1 (separate commit groups)
    #pragma unroll
    for (int p = 0; p < 2; p++) {
        if (p < nb) {
            int k0 = p << 5;
            #pragma unroll
            for (int l = 0; l < 2; l++) {
                int idx = tid + l * 256;
                int r = idx >> 2;
                int s = idx & 3;
                cp_async16(&Xs[p*128*GRS + r*GRS + s*4], X + (size_t)(bm + r) * K + k0 + s*8);
                cp_async16(&Ws[p*128*GRS + r*GRS + s*4], W + (size_t)(bn + r) * K + k0 + s*8);
            }
            cp_commit();
        }
    }

    for (int kb = 0; kb < nb; kb++) {
        const int buf = kb % 3;
        cp_wait1();              // tile kb complete (kb+1 may be in flight)
        __syncthreads();         // also guards reuse of buffer (kb+2)%3
        if (kb + 2 < nb) {
            int k0 = (kb + 2) << 5;
            int pb = (kb + 2) % 3;
            #pragma unroll
            for (int l = 0; l < 2; l++) {
                int idx = tid + l * 256;
                int r = idx >> 2;
                int s = idx & 3;
                cp_async16(&Xs[pb*128*GRS + r*GRS + s*4],
                           X + (size_t)(bm + r) * K + k0 + s*8);
                cp_async16(&Ws[pb*128*GRS + r*GRS + s*4],
                           W + (size_t)(bn + r) * K + k0 + s*8);
            }
            cp_commit();
        }

        const uint32_t* xb = Xs + buf * 128 * GRS;
        const uint32_t* wb = Ws + buf * 128 * GRS;
        #pragma unroll
        for (int s = 0; s < 2; s++) {
            const int so = s * 8;
            uint32_t afr[2][4];
            #pragma unroll
            for (int mt = 0; mt < 2; mt++) {
                int r0 = wm*32 + mt*16 + gid;
                afr[mt][0] = xb[r0*GRS + so + tg];
                afr[mt][1] = xb[(r0+8)*GRS + so + tg];
                afr[mt][2] = xb[r0*GRS + so + 4 + tg];
                afr[mt][3] = xb[(r0+8)*GRS + so + 4 + tg];
            }
            uint32_t bfr[8][2];
            #pragma unroll
            for (int nt = 0; nt < 8; nt++) {
                int nr = wn*64 + nt*8 + gid;
                bfr[nt][0] = wb[nr*GRS + so + tg];
                bfr[nt][1] = wb[nr*GRS + so + 4 + tg];
            }
            #pragma unroll
            for (int mt = 0; mt < 2; mt++)
                #pragma unroll
                for (int nt = 0; nt < 8; nt++)
                    mma_bf16(acc[mt][nt], afr[mt], bfr[nt]);
        }
    }

    __syncthreads();
    #pragma unroll
    for (int mt = 0; mt < 2; mt++) {
        int m0 = bm + wm*32 + mt*16 + gid;
        int row0 = remap ? ((m0 & (Tq-1)) * Bq + (m0 >> 9)) : m0;
        int m1 = m0 + 8;
        int row1 = remap ? ((m1 & (Tq-1)) * Bq + (m1 >> 9)) : m1;
        #pragma unroll
        for (int nt = 0; nt < 8; nt++) {
            int c0 = bn + wn*64 + nt*8 + tg*2;
            float2 bv = *(const float2*)(bias + c0);
            float2 o0, o1;
            o0.x = acc[mt][nt][0] + bv.x; o0.y = acc[mt][nt][1] + bv.y;
            o1.x = acc[mt][nt][2] + bv.x; o1.y = acc[mt][nt][3] + bv.y;
            *(float2*)(Y + (size_t)row0 * Gq + c0) = o0;
            *(float2*)(Y + (size_t)row1 * Gq + c0) = o1;
        }
    }
}

// ============================================================
// Persistent LSTM layer with bf16 tensor-core recurrent GEMM.
// 128 blocks x 256 threads. Whh slice bf16 in smem; h (bf16)
// streamed in 2 chunks of 512k, double-buffered cp.async.
// Scalar fragment loads (R13 proven). Split-half distributed-flag
// barrier: chunk-0 cp.async issued after first 64 producer flags,
// hiding producer skew + half the barrier fan-in.
// hseq written bf16 (hsb).
// ============================================================
__global__ void __launch_bounds__(256, 1)
lstm_layer(const float* __restrict__ xproj, const float* __restrict__ Whh,
           const float* __restrict__ bhh, __nv_bfloat16* __restrict__ hsb)
{
    extern __shared__ uint32_t sm2[];
    uint32_t* Wsm = sm2 + WOFF2;       // [32][WSTR]
    uint32_t* Hsm = sm2 + HOFF2;       // [2][64][HCH]
    float*    Rsm = (float*)(sm2 + ROFF2);   // [2][64][36]

    const int tid = threadIdx.x;
    const int bid = blockIdx.x;
    const int j0  = bid * 8;

    // per-launch barrier base (own flag: all blocks completed the same count)
    const unsigned base = *(volatile unsigned*)&g_flags[bid * 32];

    // ---- preload + convert weight slice to bf16 smem
    #pragma unroll
    for (int l = 0; l < 32; l++) {
        int idx = tid + l * 256;
        int c  = idx >> 8;
        int kq = idx & 255;
        int grow = (c >> 3) * Hq + j0 + (c & 7);
        float4 v = *(const float4*)(Whh + (size_t)grow * Hq + kq * 4);
        __nv_bfloat162 p0 = __floats2bfloat162_rn(v.x, v.y);
        __nv_bfloat162 p1 = __floats2bfloat162_rn(v.z, v.w);
        Wsm[c * WSTR + kq * 2]     = *(const uint32_t*)&p0;
        Wsm[c * WSTR + kq * 2 + 1] = *(const uint32_t*)&p1;
    }

    const int warp = tid >> 5;
    const int lane = tid & 31;
    const int gid = lane >> 2;
    const int tg  = lane & 3;
    const int ks  = warp & 1;
    const int wn2 = (warp >> 1) & 1;
    const int wm  = warp >> 2;

    float creg[2] = {0.0f, 0.0f};
    float bh[2][4];
    #pragma unroll
    for (int q = 0; q < 2; q++) {
        int p = tid + q * 256;
        int jl = p & 7;
        #pragma unroll
        for (int g2 = 0; g2 < 4; g2++) bh[q][g2] = bhh[g2 * Hq + j0 + jl];
    }

    ((uint32_t*)g_hbufb[0])[bid * 256 + tid] = 0u;
    __syncthreads();
    if (tid == 0) {
        __threadfence();
        *(volatile unsigned*)&g_flags[bid * 32] = base + 1;
    }

    for (int t = 0; t < Tq; t++) {
        const __nv_bfloat16* hprev = g_hbufb[t & 1];
        __nv_bfloat16* hnext = g_hbufb[(t + 1) & 1];
        const unsigned target = base + t + 1;

        // wait for first-half producers (h cols 0-511 = blocks 0-63)
        if (tid < 64) {
            while (*(volatile unsigned*)&g_flags[tid * 32] < target) { }
        }
        __syncthreads();
        __threadfence();   // acquire: order subsequent loads after flag observation

        // prefetch chunk 0 (64 rows x 512 bf16) into buf 0
        #pragma unroll
        for (int l = 0; l < 16; l++) {
            int idx = tid + l * 256;
            int row = idx >> 6;
            int seg = idx & 63;
            cp_async16(Hsm + row * HCH + seg * 4,
                       hprev + (size_t)row * Hq + seg * 8);
        }
        cp_commit();

        // wait for second-half producers (blocks 64-127) while chunk0 flies
        if (tid < 64) {
            while (*(volatile unsigned*)&g_flags[(64 + tid) * 32] < target) { }
        }
        __syncthreads();
        __threadfence();

        // prefetch this step's xproj gate values
        float xg[2][4];
        #pragma unroll
        for (int q = 0; q < 2; q++) {
            int p = tid + q * 256;
            int b = p >> 3, jl = p & 7;
            size_t xb = ((size_t)t * Bq + b) * Gq + j0 + jl;
            #pragma unroll
            for (int g2 = 0; g2 < 4; g2++) xg[q][g2] = xproj[xb + (size_t)g2 * Hq];
        }

        float acc[2][2][4] = {};
        for (int kc = 0; kc < 2; kc++) {
            const int buf = kc & 1;
            cp_wait0();
            __syncthreads();
            if (kc == 0) {
                uint32_t* hdst = Hsm + HCHBUF;
                #pragma unroll
                for (int l = 0; l < 16; l++) {
                    int idx = tid + l * 256;
                    int row = idx >> 6;
                    int seg = idx & 63;
                    cp_async16(hdst + row * HCH + seg * 4,
                               hprev + (size_t)row * Hq + 512 + seg * 8);
                }
                cp_commit();
            }

            const uint32_t* hb = Hsm + buf * HCHBUF;
            #pragma unroll
            for (int step = 0; step < 16; step++) {
                int kwc = ks * 128 + step * 8;
                int kww = kc * 256 + kwc;
                uint32_t afr[2][4];
                #pragma unroll
                for (int mt = 0; mt < 2; mt++) {
                    int r0 = wm * 32 + mt * 16 + gid;
                    afr[mt][0] = hb[r0 * HCH + kwc + tg];
                    afr[mt][1] = hb[(r0 + 8) * HCH + kwc + tg];
                    afr[mt][2] = hb[r0 * HCH + kwc + 4 + tg];
                    afr[mt][3] = hb[(r0 + 8) * HCH + kwc + 4 + tg];
                }
                uint32_t bfr[2][2];
                #pragma unroll
                for (int nt = 0; nt < 2; nt++) {
                    int nr = wn2 * 16 + nt * 8 + gid;
                    bfr[nt][0] = Wsm[nr * WSTR + kww + tg];
                    bfr[nt][1] = Wsm[nr * WSTR + kww + 4 + tg];
                }
                #pragma unroll
                for (int mt = 0; mt < 2; mt++)
                    #pragma unroll
                    for (int nt = 0; nt < 2; nt++)
                        mma_bf16(acc[mt][nt], afr[mt], bfr[nt]);
            }
        }

        // stash fp32 partials: Rsm[ks][row][col]
        #pragma unroll
        for (int mt = 0; mt < 2; mt++) {
            int r = wm * 32 + mt * 16 + gid;
            #pragma unroll
            for (int nt = 0; nt < 2; nt++) {
                int c = wn2 * 16 + nt * 8 + tg * 2;
                Rsm[ks * 2304 + r * 36 + c]           = acc[mt][nt][0];
                Rsm[ks * 2304 + r * 36 + c + 1]       = acc[mt][nt][1];
                Rsm[ks * 2304 + (r + 8) * 36 + c]     = acc[mt][nt][2];
                Rsm[ks * 2304 + (r + 8) * 36 + c + 1] = acc[mt][nt][3];
            }
        }
        __syncthreads();

        // pointwise LSTM update (2 items per thread)
        #pragma unroll
        for (int q = 0; q < 2; q++) {
            int p = tid + q * 256;
            int b = p >> 3, jl = p & 7;
            const float* r0p = Rsm + b * 36;
            const float* r1p = Rsm + 2304 + b * 36;
            float gi = r0p[jl]      + r1p[jl]      + xg[q][0] + bh[q][0];
            float gf = r0p[8 + jl]  + r1p[8 + jl]  + xg[q][1] + bh[q][1];
            float gg = r0p[16 + jl] + r1p[16 + jl] + xg[q][2] + bh[q][2];
            float go = r0p[24 + jl] + r1p[24 + jl] + xg[q][3] + bh[q][3];
            float ig = 1.0f / (1.0f + expf(-gi));
            float fg = 1.0f / (1.0f + expf(-gf));
            float gv = tanhf(gg);
            float og = 1.0f / (1.0f + expf(-go));
            float cn = fg * creg[q] + ig * gv;
            creg[q] = cn;
            float hn = og * tanhf(cn);
            __nv_bfloat16 hb16 = __float2bfloat16(hn);
            hnext[(size_t)b * Hq + j0 + jl] = hb16;
            hsb[((size_t)t * Bq + b) * Hq + j0 + jl] = hb16;
        }

        // signal completion of h(t+1) for this block
        __syncthreads();
        if (tid == 0) {
            __threadfence();
            *(volatile unsigned*)&g_flags[bid * 32] = base + t + 2;
        }
    }
}

// ============================================================
// Emissions: e[(t*B+b), c] = h2_row . fc_w[c] + fc_b[c]; one warp/row.
// h2 is bf16; loads packed bf16x2.
// ============================================================
__global__ void emis_kernel(const __nv_bfloat16* __restrict__ h2,
                            const float* __restrict__ fcw,
                            const float* __restrict__ fcb, float* __restrict__ e)
{
    int warp = (blockIdx.x * blockDim.x + threadIdx.x) >> 5;
    int lane = threadIdx.x & 31;
    if (warp >= MTOT) return;
    const uint32_t* hr = (const uint32_t*)(h2 + (size_t)warp * Hq);
    float acc[Cq];
    #pragma unroll
    for (int cc = 0; cc < Cq; cc++) acc[cc] = 0.0f;
    for (int k2 = lane; k2 < Hq/2; k2 += 32) {
        uint32_t pv = hr[k2];
        __nv_bfloat162 p = *(const __nv_bfloat162*)&pv;
        float h0 = __bfloat162float(p.x);
        float h1 = __bfloat162float(p.y);
        int k = k2 * 2;
        #pragma unroll
        for (int cc = 0; cc < Cq; cc++) {
            acc[cc] = fmaf(h0, fcw[cc*Hq + k], acc[cc]);
            acc[cc] = fmaf(h1, fcw[cc*Hq + k + 1], acc[cc]);
        }
    }
    #pragma unroll
    for (int cc = 0; cc < Cq; cc++) {
        float v = acc[cc];
        #pragma unroll
        for (int off = 16; off; off >>= 1) v += __shfl_down_sync(0xffffffffu, v, off);
        if (lane == 0) e[(size_t)warp * Cq + cc] = v + fcb[cc];
    }
}

// ============================================================
// CRF NLL per batch element. One warp per b. emissions in (T,B,C).
// ============================================================
__global__ void crf_kernel(const float* __restrict__ e, const int* __restrict__ labels,
                           const float* __restrict__ startt, const float* __restrict__ endt,
                           const float* __restrict__ trans, float* __restrict__ llh)
{
    int b = blockIdx.x;
    int lane = threadIdx.x;
    const int* lb = labels + (size_t)b * Tq;

    // ---- path score ----
    float part = 0.0f;
    int cnt = 0;
    for (int t = 1 + lane; t < Tq; t += 32) {
        int tag  = lb[t];
        int tagp = lb[t-1];
        if (tag != -1)
            part += trans[tagp*Cq + tag] + e[((size_t)t*Bq + b)*Cq + tag];
    }
    for (int t = lane; t < Tq; t += 32) cnt += (lb[t] != -1);
    #pragma unroll
    for (int off = 16; off; off >>= 1) {
        part += __shfl_down_sync(0xffffffffu, part, off);
        cnt  += __shfl_down_sync(0xffffffffu, cnt, off);
    }
    float score = 0.0f;
    if (lane == 0) {
        int tag0 = lb[0];
        score = startt[tag0] + e[(size_t)b*Cq + tag0] + part;
        int last = cnt - 1;
        score += endt[lb[last]];
    }

    // ---- logZ (forward algorithm) ----
    __shared__ float alpha[Cq];
    float tcol[Cq];
    if (lane < Cq) {
        #pragma unroll
        for (int cc = 0; cc < Cq; cc++) tcol[cc] = trans[cc*Cq + lane];
        alpha[lane] = startt[lane] + e[(size_t)b*Cq + lane];
    }
    __syncwarp();
    for (int t = 1; t < Tq; t++) {
        bool m = (lb[t] != -1);
        float av[Cq];
        #pragma unroll
        for (int cc = 0; cc < Cq; cc++) av[cc] = alpha[cc];
        float nxt = 0.0f;
        if (lane < Cq) {
            float mx = -1e30f;
            #pragma unroll
            for (int cc = 0; cc < Cq; cc++) mx = fmaxf(mx, av[cc] + tcol[cc]);
            float s = 0.0f;
            #pragma unroll
            for (int cc = 0; cc < Cq; cc++) s += expf(av[cc] + tcol[cc] - mx);
            nxt = mx + logf(s) + e[((size_t)t*Bq + b)*Cq + lane];
        }
        __syncwarp();
        if (m && lane < Cq) alpha[lane] = nxt;
        __syncwarp();
    }
    float v = (lane < Cq) ? alpha[lane] + endt[lane] : -1e30f;
    float mx = v;
    #pragma unroll
    for (int off = 16; off; off >>= 1) mx = fmaxf(mx, __shfl_xor_sync(0xffffffffu, mx, off));
    float sv = (lane < Cq) ? expf(v - mx) : 0.0f;
    #pragma unroll
    for (int off = 16; off; off >>= 1) sv += __shfl_xor_sync(0xffffffffu, sv, off);
    if (lane == 0) llh[b] = score - (mx + logf(sv));
}

__global__ void finalize_kernel(const float* __restrict__ llh, float* __restrict__ out)
{
    __shared__ float s[64];
    int lane = threadIdx.x;
    s[lane] = llh[lane];
    __syncthreads();
    #pragma unroll
    for (int off = 32; off; off >>= 1) {
        if (lane < off) s[lane] += s[lane + off];
        __syncthreads();
    }
    if (lane == 0) out[0] = -s[0] / (float)Bq;
}

// ============================================================
extern "C" void kernel_launch(void* const* d_in, const int* in_sizes, int n_in,
                              void* d_out, int out_size)
{
    const float* x     = (const float*)d_in[0];
    const int*   labels= (const int*)  d_in[1];
    // d_in[2] = lengths (unused; reference derives mask from labels)
    const float* Wih0  = (const float*)d_in[3];
    const float* Whh0  = (const float*)d_in[4];
    const float* bih0  = (const float*)d_in[5];
    const float* bhh0  = (const float*)d_in[6];
    const float* Wih1  = (const float*)d_in[7];
    const float* Whh1  = (const float*)d_in[8];
    const float* bih1  = (const float*)d_in[9];
    const float* bhh1  = (const float*)d_in[10];
    const float* fcw   = (const float*)d_in[11];
    const float* fcb   = (const float*)d_in[12];
    const float* startt= (const float*)d_in[13];
    const float* endt  = (const float*)d_in[14];
    const float* trans = (const float*)d_in[15];

    float *xproj, *emis, *llh;
    __nv_bfloat16 *xb, *wb, *hs2b;
    cudaGetSymbolAddress((void**)&xproj, g_xproj);
    cudaGetSymbolAddress((void**)&hs2b,  g_hs2b);
    cudaGetSymbolAddress((void**)&xb,    g_xb);
    cudaGetSymbolAddress((void**)&wb,    g_wb);
    cudaGetSymbolAddress((void**)&emis,  g_emis);
    cudaGetSymbolAddress((void**)&llh,   g_llh);

    cudaFuncSetAttribute(lstm_layer, cudaFuncAttributeMaxDynamicSharedMemorySize, LSTM_SMEM_BYTES);
    cudaFuncSetAttribute(sgemm_bf16, cudaFuncAttributeMaxDynamicSharedMemorySize, GEMM_SMEM_BYTES);

    dim3 gsX(Gq/128, MTOT/128);      // (32, 256)

    // ---- layer 1 ----
    cvt_bf16<<<(MTOT*Iq/4 + 255)/256, 256>>>(x, xb, MTOT*Iq/4);
    cvt_bf16<<<(Gq*Iq/4 + 255)/256, 256>>>(Wih0, wb, Gq*Iq/4);
    sgemm_bf16<<<gsX, 256, GEMM_SMEM_BYTES>>>(xb, wb, bih0, xproj, Iq, /*remap=*/1);
    // layer-1 hseq written as bf16 into xb (rows t*B+b) -> feeds layer-2 GEMM
    lstm_layer<<<NBLK, 256, LSTM_SMEM_BYTES>>>(xproj, Whh0, bhh0, xb);

    // ---- layer 2 ----
    cvt_bf16<<<(Gq*Hq/4 + 255)/256, 256>>>(Wih1, wb, Gq*Hq/4);
    sgemm_bf16<<<gsX, 256, GEMM_SMEM_BYTES>>>(xb, wb, bih1, xproj, Hq, /*remap=*/0);
    lstm_layer<<<NBLK, 256, LSTM_SMEM_BYTES>>>(xproj, Whh1, bhh1, hs2b);

    // ---- emissions + CRF ----
    emis_kernel<<<(MTOT*32)/256, 256>>>(hs2b, fcw, fcb, emis);
    crf_kernel<<<Bq, 32>>>(emis, labels, startt, endt, trans, llh);
    finalize_kernel<<<1, 64>>>(llh, (float*)d_out);
}

// round 17
// speedup vs baseline: 1.1137x; 1.1137x over previous
#include <cuda_runtime.h>
#include <cuda_bf16.h>
#include <math.h>
#include <stdint.h>

// Problem constants
#define Bq 64
#define Tq 512
#define Iq 512
#define Hq 1024
#define Gq 4096      // 4*H
#define Cq 20
#define MTOT (Bq*Tq) // 32768
#define NBLK 128     // persistent blocks (<148 => all co-resident)

// sgemm_bf16 smem (uint32 words): 3-stage Xs[3][128][20] + Ws[3][128][20]
#define GRS 20
#define GEMM_SMEM_WORDS (3*128*GRS + 3*128*GRS)
#define GEMM_SMEM_BYTES (GEMM_SMEM_WORDS * 4)    // 61440

// lstm_layer smem layout (uint32 words)
#define WSTR 516
#define HCH  260
#define HCHBUF (64*HCH)           // 16640 words
#define WOFF2 0
#define HOFF2 (32*WSTR)           // 16512
#define ROFF2 (HOFF2 + 2*HCHBUF)  // 49792
#define LSTM_SMEM_WORDS (ROFF2 + 2*64*36)
#define LSTM_SMEM_BYTES (LSTM_SMEM_WORDS * 4)    // 217600

// ---- scratch (static device allocations; no cudaMalloc allowed) ----
__device__ float g_xproj[(size_t)MTOT * Gq];   // 512 MB, reused by both layers
__device__ __nv_bfloat16 g_hs2b[(size_t)MTOT * Hq];  // 67 MB bf16 layer-2 hseq
__device__ __nv_bfloat16 g_xb[(size_t)MTOT * Hq];    // 64 MB bf16
__device__ __nv_bfloat16 g_wb[(size_t)Gq * Hq];      // 8 MB bf16 weights
__device__ __nv_bfloat16 g_hbufb[2][Bq * Hq];  // h ping-pong (bf16)
__device__ float g_emis[(size_t)MTOT * Cq];    // (T,B,C)
__device__ float g_llh[Bq];
__device__ unsigned g_flags[NBLK * 32];        // distributed barrier flags (128B apart)

__device__ __forceinline__ void cp_async16(void* smem_dst, const void* gmem_src)
{
    uint32_t s = (uint32_t)__cvta_generic_to_shared(smem_dst);
    asm volatile("cp.async.cg.shared.global [%0], [%1], 16;\n" :: "r"(s), "l"(gmem_src));
}
__device__ __forceinline__ void cp_commit()
{
    asm volatile("cp.async.commit_group;\n");
}
__device__ __forceinline__ void cp_wait0()
{
    asm volatile("cp.async.wait_group 0;\n");
}
__device__ __forceinline__ void cp_wait1()
{
    asm volatile("cp.async.wait_group 1;\n");
}

// bf16 MMA: D(16x8,f32) += A(16x16,row,bf16) * B(16x8,col,bf16)
__device__ __forceinline__ void mma_bf16(float* d, const uint32_t* a, const uint32_t* b)
{
    asm volatile(
        "mma.sync.aligned.m16n8k16.row.col.f32.bf16.bf16.f32 "
        "{%0,%1,%2,%3}, {%4,%5,%6,%7}, {%8,%9}, {%0,%1,%2,%3};"
        : "+f"(d[0]), "+f"(d[1]), "+f"(d[2]), "+f"(d[3])
        : "r"(a[0]), "r"(a[1]), "r"(a[2]), "r"(a[3]), "r"(b[0]), "r"(b[1]));
}

// ============================================================
// Elementwise fp32 -> bf16.
// ============================================================
__global__ void cvt_bf16(const float* __restrict__ src, __nv_bfloat16* __restrict__ dst,
                         int nquads)
{
    int i = blockIdx.x * blockDim.x + threadIdx.x;
    if (i >= nquads) return;
    float4 v = *(const float4*)(src + (size_t)i * 4);
    __nv_bfloat162 p0 = __floats2bfloat162_rn(v.x, v.y);
    __nv_bfloat162 p1 = __floats2bfloat162_rn(v.z, v.w);
    uint2 o;
    o.x = *(const uint32_t*)&p0;
    o.y = *(const uint32_t*)&p1;
    *(uint2*)(dst + (size_t)i * 4) = o;
}

// ============================================================
// bf16 tensor-core GEMM: Y = X(MxK)*W(NxK)^T + bias (fp32 out)
// Block tile 128m x 128n, BK=32, 256 threads (8 warps),
// warp tile 32m x 64n, m16n8k16, 3-stage cp.async pipeline
// (wait_group 1), 2 CTAs/SM. (R13 proven configuration.)
// If remap!=0, X row m = b*T+t and output row becomes t*B+b.
// ============================================================
__global__ void __launch_bounds__(256, 2)
sgemm_bf16(const __nv_bfloat16* __restrict__ X, const __nv_bfloat16* __restrict__ W,
           const float* __restrict__ bias, float* __restrict__ Y,
           int K, int remap)
{
    extern __shared__ uint32_t gsm[];
    uint32_t* Xs = gsm;                 // [3][128][GRS]
    uint32_t* Ws = gsm + 3 * 128 * GRS; // [3][128][GRS]

    const int bn = blockIdx.x * 128;
    const int bm = blockIdx.y * 128;
    const int tid = threadIdx.x;
    const int warp = tid >> 5;
    const int lane = tid & 31;
    const int gid = lane >> 2;
    const int tg  = lane & 3;
    const int wm = warp >> 1;        // 0..3 -> m0 = wm*32
    const int wn = warp & 1;         // 0..1 -> n0 = wn*64

    float acc[2][8][4] = {};
    const int nb = K >> 5;

    // prefetch tiles 0 and 1 (separate commit groups)
    #pragma unroll
    for (int p = 0; p < 2; p++) {
        if (p < nb) {
            int k0 = p << 5;
            #pragma unroll
            for (int l = 0; l < 2; l++) {
                int idx = tid + l * 256;
                int r = idx >> 2;
                int s = idx & 3;
                cp_async16(&Xs[p*128*GRS + r*GRS + s*4], X + (size_t)(bm + r) * K + k0 + s*8);
                cp_async16(&Ws[p*128*GRS + r*GRS + s*4], W + (size_t)(bn + r) * K + k0 + s*8);
            }
            cp_commit();
        }
    }

    for (int kb = 0; kb < nb; kb++) {
        const int buf = kb % 3;
        cp_wait1();              // tile kb complete (kb+1 may be in flight)
        __syncthreads();         // also guards reuse of buffer (kb+2)%3
        if (kb + 2 < nb) {
            int k0 = (kb + 2) << 5;
            int pb = (kb + 2) % 3;
            #pragma unroll
            for (int l = 0; l < 2; l++) {
                int idx = tid + l * 256;
                int r = idx >> 2;
                int s = idx & 3;
                cp_async16(&Xs[pb*128*GRS + r*GRS + s*4],
                           X + (size_t)(bm + r) * K + k0 + s*8);
                cp_async16(&Ws[pb*128*GRS + r*GRS + s*4],
                           W + (size_t)(bn + r) * K + k0 + s*8);
            }
            cp_commit();
        }

        const uint32_t* xb = Xs + buf * 128 * GRS;
        const uint32_t* wb = Ws + buf * 128 * GRS;
        #pragma unroll
        for (int s = 0; s < 2; s++) {
            const int so = s * 8;
            uint32_t afr[2][4];
            #pragma unroll
            for (int mt = 0; mt < 2; mt++) {
                int r0 = wm*32 + mt*16 + gid;
                afr[mt][0] = xb[r0*GRS + so + tg];
                afr[mt][1] = xb[(r0+8)*GRS + so + tg];
                afr[mt][2] = xb[r0*GRS + so + 4 + tg];
                afr[mt][3] = xb[(r0+8)*GRS + so + 4 + tg];
            }
            uint32_t bfr[8][2];
            #pragma unroll
            for (int nt = 0; nt < 8; nt++) {
                int nr = wn*64 + nt*8 + gid;
                bfr[nt][0] = wb[nr*GRS + so + tg];
                bfr[nt][1] = wb[nr*GRS + so + 4 + tg];
            }
            #pragma unroll
            for (int mt = 0; mt < 2; mt++)
                #pragma unroll
                for (int nt = 0; nt < 8; nt++)
                    mma_bf16(acc[mt][nt], afr[mt], bfr[nt]);
        }
    }

    __syncthreads();
    #pragma unroll
    for (int mt = 0; mt < 2; mt++) {
        int m0 = bm + wm*32 + mt*16 + gid;
        int row0 = remap ? ((m0 & (Tq-1)) * Bq + (m0 >> 9)) : m0;
        int m1 = m0 + 8;
        int row1 = remap ? ((m1 & (Tq-1)) * Bq + (m1 >> 9)) : m1;
        #pragma unroll
        for (int nt = 0; nt < 8; nt++) {
            int c0 = bn + wn*64 + nt*8 + tg*2;
            float2 bv = *(const float2*)(bias + c0);
            float2 o0, o1;
            o0.x = acc[mt][nt][0] + bv.x; o0.y = acc[mt][nt][1] + bv.y;
            o1.x = acc[mt][nt][2] + bv.x; o1.y = acc[mt][nt][3] + bv.y;
            *(float2*)(Y + (size_t)row0 * Gq + c0) = o0;
            *(float2*)(Y + (size_t)row1 * Gq + c0) = o1;
        }
    }
}

// ============================================================
// Simple distributed-flag grid barrier (R13 proven): arrival =
// one release store; wait = 128 threads each polling one flag.
// ============================================================
__device__ __forceinline__ void gridbar_flags(int bid, unsigned target)
{
    __syncthreads();
    if (threadIdx.x == 0) {
        __threadfence();
        *(volatile unsigned*)&g_flags[bid * 32] = target;
    }
    if (threadIdx.x < NBLK) {
        while (*(volatile unsigned*)&g_flags[threadIdx.x * 32] < target) { }
        __threadfence();
    }
    __syncthreads();
}

// ============================================================
// Persistent LSTM layer with bf16 tensor-core recurrent GEMM.
// 128 blocks x 256 threads. Whh slice bf16 in smem; h (bf16)
// streamed in 2 chunks of 512k, double-buffered cp.async.
// Scalar fragment loads; simple flag barrier (R13 proven).
// hseq written bf16 (hsb).
// ============================================================
__global__ void __launch_bounds__(256, 1)
lstm_layer(const float* __restrict__ xproj, const float* __restrict__ Whh,
           const float* __restrict__ bhh, __nv_bfloat16* __restrict__ hsb)
{
    extern __shared__ uint32_t sm2[];
    uint32_t* Wsm = sm2 + WOFF2;       // [32][WSTR]
    uint32_t* Hsm = sm2 + HOFF2;       // [2][64][HCH]
    float*    Rsm = (float*)(sm2 + ROFF2);   // [2][64][36]

    const int tid = threadIdx.x;
    const int bid = blockIdx.x;
    const int j0  = bid * 8;

    const unsigned base = *(volatile unsigned*)&g_flags[bid * 32];
    unsigned bcnt = 0;

    // ---- preload + convert weight slice to bf16 smem
    #pragma unroll
    for (int l = 0; l < 32; l++) {
        int idx = tid + l * 256;
        int c  = idx >> 8;
        int kq = idx & 255;
        int grow = (c >> 3) * Hq + j0 + (c & 7);
        float4 v = *(const float4*)(Whh + (size_t)grow * Hq + kq * 4);
        __nv_bfloat162 p0 = __floats2bfloat162_rn(v.x, v.y);
        __nv_bfloat162 p1 = __floats2bfloat162_rn(v.z, v.w);
        Wsm[c * WSTR + kq * 2]     = *(const uint32_t*)&p0;
        Wsm[c * WSTR + kq * 2 + 1] = *(const uint32_t*)&p1;
    }

    const int warp = tid >> 5;
    const int lane = tid & 31;
    const int gid = lane >> 2;
    const int tg  = lane & 3;
    const int ks  = warp & 1;
    const int wn2 = (warp >> 1) & 1;
    const int wm  = warp >> 2;

    float creg[2] = {0.0f, 0.0f};
    float bh[2][4];
    #pragma unroll
    for (int q = 0; q < 2; q++) {
        int p = tid + q * 256;
        int jl = p & 7;
        #pragma unroll
        for (int g2 = 0; g2 < 4; g2++) bh[q][g2] = bhh[g2 * Hq + j0 + jl];
    }

    ((uint32_t*)g_hbufb[0])[bid * 256 + tid] = 0u;
    bcnt++;
    gridbar_flags(bid, base + bcnt);

    for (int t = 0; t < Tq; t++) {
        const __nv_bfloat16* hprev = g_hbufb[t & 1];
        __nv_bfloat16* hnext = g_hbufb[(t + 1) & 1];

        // prefetch chunk 0 (64 rows x 512 bf16) into buf 0
        #pragma unroll
        for (int l = 0; l < 16; l++) {
            int idx = tid + l * 256;
            int row = idx >> 6;
            int seg = idx & 63;
            cp_async16(Hsm + row * HCH + seg * 4,
                       hprev + (size_t)row * Hq + seg * 8);
        }
        cp_commit();

        // prefetch this step's xproj gate values (hidden behind GEMM)
        float xg[2][4];
        #pragma unroll
        for (int q = 0; q < 2; q++) {
            int p = tid + q * 256;
            int b = p >> 3, jl = p & 7;
            size_t xb = ((size_t)t * Bq + b) * Gq + j0 + jl;
            #pragma unroll
            for (int g2 = 0; g2 < 4; g2++) xg[q][g2] = xproj[xb + (size_t)g2 * Hq];
        }

        float acc[2][2][4] = {};
        for (int kc = 0; kc < 2; kc++) {
            const int buf = kc & 1;
            cp_wait0();
            __syncthreads();
            if (kc == 0) {
                uint32_t* hdst = Hsm + HCHBUF;
                #pragma unroll
                for (int l = 0; l < 16; l++) {
                    int idx = tid + l * 256;
                    int row = idx >> 6;
                    int seg = idx & 63;
                    cp_async16(hdst + row * HCH + seg * 4,
                               hprev + (size_t)row * Hq + 512 + seg * 8);
                }
                cp_commit();
            }

            const uint32_t* hb = Hsm + buf * HCHBUF;
            #pragma unroll
            for (int step = 0; step < 16; step++) {
                int kwc = ks * 128 + step * 8;
                int kww = kc * 256 + kwc;
                uint32_t afr[2][4];
                #pragma unroll
                for (int mt = 0; mt < 2; mt++) {
                    int r0 = wm * 32 + mt * 16 + gid;
                    afr[mt][0] = hb[r0 * HCH + kwc + tg];
                    afr[mt][1] = hb[(r0 + 8) * HCH + kwc + tg];
                    afr[mt][2] = hb[r0 * HCH + kwc + 4 + tg];
                    afr[mt][3] = hb[(r0 + 8) * HCH + kwc + 4 + tg];
                }
                uint32_t bfr[2][2];
                #pragma unroll
                for (int nt = 0; nt < 2; nt++) {
                    int nr = wn2 * 16 + nt * 8 + gid;
                    bfr[nt][0] = Wsm[nr * WSTR + kww + tg];
                    bfr[nt][1] = Wsm[nr * WSTR + kww + 4 + tg];
                }
                #pragma unroll
                for (int mt = 0; mt < 2; mt++)
                    #pragma unroll
                    for (int nt = 0; nt < 2; nt++)
                        mma_bf16(acc[mt][nt], afr[mt], bfr[nt]);
            }
        }

        // stash fp32 partials: Rsm[ks][row][col]
        #pragma unroll
        for (int mt = 0; mt < 2; mt++) {
            int r = wm * 32 + mt * 16 + gid;
            #pragma unroll
            for (int nt = 0; nt < 2; nt++) {
                int c = wn2 * 16 + nt * 8 + tg * 2;
                Rsm[ks * 2304 + r * 36 + c]           = acc[mt][nt][0];
                Rsm[ks * 2304 + r * 36 + c + 1]       = acc[mt][nt][1];
                Rsm[ks * 2304 + (r + 8) * 36 + c]     = acc[mt][nt][2];
                Rsm[ks * 2304 + (r + 8) * 36 + c + 1] = acc[mt][nt][3];
            }
        }
        __syncthreads();

        // pointwise LSTM update (2 items per thread)
        #pragma unroll
        for (int q = 0; q < 2; q++) {
            int p = tid + q * 256;
            int b = p >> 3, jl = p & 7;
            const float* r0p = Rsm + b * 36;
            const float* r1p = Rsm + 2304 + b * 36;
            float gi = r0p[jl]      + r1p[jl]      + xg[q][0] + bh[q][0];
            float gf = r0p[8 + jl]  + r1p[8 + jl]  + xg[q][1] + bh[q][1];
            float gg = r0p[16 + jl] + r1p[16 + jl] + xg[q][2] + bh[q][2];
            float go = r0p[24 + jl] + r1p[24 + jl] + xg[q][3] + bh[q][3];
            float ig = 1.0f / (1.0f + expf(-gi));
            float fg = 1.0f / (1.0f + expf(-gf));
            float gv = tanhf(gg);
            float og = 1.0f / (1.0f + expf(-go));
            float cn = fg * creg[q] + ig * gv;
            creg[q] = cn;
            float hn = og * tanhf(cn);
            __nv_bfloat16 hb16 = __float2bfloat16(hn);
            hnext[(size_t)b * Hq + j0 + jl] = hb16;
            hsb[((size_t)t * Bq + b) * Hq + j0 + jl] = hb16;
        }
        bcnt++;
        gridbar_flags(bid, base + bcnt);
    }
}

// ============================================================
// Emissions: e[(t*B+b), c] = h2_row . fc_w[c] + fc_b[c]; one warp/row.
// h2 is bf16; loads packed bf16x2.
// ============================================================
__global__ void emis_kernel(const __nv_bfloat16* __restrict__ h2,
                            const float* __restrict__ fcw,
                            const float* __restrict__ fcb, float* __restrict__ e)
{
    int warp = (blockIdx.x * blockDim.x + threadIdx.x) >> 5;
    int lane = threadIdx.x & 31;
    if (warp >= MTOT) return;
    const uint32_t* hr = (const uint32_t*)(h2 + (size_t)warp * Hq);
    float acc[Cq];
    #pragma unroll
    for (int cc = 0; cc < Cq; cc++) acc[cc] = 0.0f;
    for (int k2 = lane; k2 < Hq/2; k2 += 32) {
        uint32_t pv = hr[k2];
        __nv_bfloat162 p = *(const __nv_bfloat162*)&pv;
        float h0 = __bfloat162float(p.x);
        float h1 = __bfloat162float(p.y);
        int k = k2 * 2;
        #pragma unroll
        for (int cc = 0; cc < Cq; cc++) {
            acc[cc] = fmaf(h0, fcw[cc*Hq + k], acc[cc]);
            acc[cc] = fmaf(h1, fcw[cc*Hq + k + 1], acc[cc]);
        }
    }
    #pragma unroll
    for (int cc = 0; cc < Cq; cc++) {
        float v = acc[cc];
        #pragma unroll
        for (int off = 16; off; off >>= 1) v += __shfl_down_sync(0xffffffffu, v, off);
        if (lane == 0) e[(size_t)warp * Cq + cc] = v + fcb[cc];
    }
}

// ============================================================
// CRF NLL per batch element. One warp per b. emissions in (T,B,C).
// ============================================================
__global__ void crf_kernel(const float* __restrict__ e, const int* __restrict__ labels,
                           const float* __restrict__ startt, const float* __restrict__ endt,
                           const float* __restrict__ trans, float* __restrict__ llh)
{
    int b = blockIdx.x;
    int lane = threadIdx.x;
    const int* lb = labels + (size_t)b * Tq;

    // ---- path score ----
    float part = 0.0f;
    int cnt = 0;
    for (int t = 1 + lane; t < Tq; t += 32) {
        int tag  = lb[t];
        int tagp = lb[t-1];
        if (tag != -1)
            part += trans[tagp*Cq + tag] + e[((size_t)t*Bq + b)*Cq + tag];
    }
    for (int t = lane; t < Tq; t += 32) cnt += (lb[t] != -1);
    #pragma unroll
    for (int off = 16; off; off >>= 1) {
        part += __shfl_down_sync(0xffffffffu, part, off);
        cnt  += __shfl_down_sync(0xffffffffu, cnt, off);
    }
    float score = 0.0f;
    if (lane == 0) {
        int tag0 = lb[0];
        score = startt[tag0] + e[(size_t)b*Cq + tag0] + part;
        int last = cnt - 1;
        score += endt[lb[last]];
    }

    // ---- logZ (forward algorithm) ----
    __shared__ float alpha[Cq];
    float tcol[Cq];
    if (lane < Cq) {
        #pragma unroll
        for (int cc = 0; cc < Cq; cc++) tcol[cc] = trans[cc*Cq + lane];
        alpha[lane] = startt[lane] + e[(size_t)b*Cq + lane];
    }
    __syncwarp();
    for (int t = 1; t < Tq; t++) {
        bool m = (lb[t] != -1);
        float av[Cq];
        #pragma unroll
        for (int cc = 0; cc < Cq; cc++) av[cc] = alpha[cc];
        float nxt = 0.0f;
        if (lane < Cq) {
            float mx = -1e30f;
            #pragma unroll
            for (int cc = 0; cc < Cq; cc++) mx = fmaxf(mx, av[cc] + tcol[cc]);
            float s = 0.0f;
            #pragma unroll
            for (int cc = 0; cc < Cq; cc++) s += expf(av[cc] + tcol[cc] - mx);
            nxt = mx + logf(s) + e[((size_t)t*Bq + b)*Cq + lane];
        }
        __syncwarp();
        if (m && lane < Cq) alpha[lane] = nxt;
        __syncwarp();
    }
    float v = (lane < Cq) ? alpha[lane] + endt[lane] : -1e30f;
    float mx = v;
    #pragma unroll
    for (int off = 16; off; off >>= 1) mx = fmaxf(mx, __shfl_xor_sync(0xffffffffu, mx, off));
    float sv = (lane < Cq) ? expf(v - mx) : 0.0f;
    #pragma unroll
    for (int off = 16; off; off >>= 1) sv += __shfl_xor_sync(0xffffffffu, sv, off);
    if (lane == 0) llh[b] = score - (mx + logf(sv));
}

__global__ void finalize_kernel(const float* __restrict__ llh, float* __restrict__ out)
{
    __shared__ float s[64];
    int lane = threadIdx.x;
    s[lane] = llh[lane];
    __syncthreads();
    #pragma unroll
    for (int off = 32; off; off >>= 1) {
        if (lane < off) s[lane] += s[lane + off];
        __syncthreads();
    }
    if (lane == 0) out[0] = -s[0] / (float)Bq;
}

// ============================================================
extern "C" void kernel_launch(void* const* d_in, const int* in_sizes, int n_in,
                              void* d_out, int out_size)
{
    const float* x     = (const float*)d_in[0];
    const int*   labels= (const int*)  d_in[1];
    // d_in[2] = lengths (unused; reference derives mask from labels)
    const float* Wih0  = (const float*)d_in[3];
    const float* Whh0  = (const float*)d_in[4];
    const float* bih0  = (const float*)d_in[5];
    const float* bhh0  = (const float*)d_in[6];
    const float* Wih1  = (const float*)d_in[7];
    const float* Whh1  = (const float*)d_in[8];
    const float* bih1  = (const float*)d_in[9];
    const float* bhh1  = (const float*)d_in[10];
    const float* fcw   = (const float*)d_in[11];
    const float* fcb   = (const float*)d_in[12];
    const float* startt= (const float*)d_in[13];
    const float* endt  = (const float*)d_in[14];
    const float* trans = (const float*)d_in[15];

    float *xproj, *emis, *llh;
    __nv_bfloat16 *xb, *wb, *hs2b;
    cudaGetSymbolAddress((void**)&xproj, g_xproj);
    cudaGetSymbolAddress((void**)&hs2b,  g_hs2b);
    cudaGetSymbolAddress((void**)&xb,    g_xb);
    cudaGetSymbolAddress((void**)&wb,    g_wb);
    cudaGetSymbolAddress((void**)&emis,  g_emis);
    cudaGetSymbolAddress((void**)&llh,   g_llh);

    cudaFuncSetAttribute(lstm_layer, cudaFuncAttributeMaxDynamicSharedMemorySize, LSTM_SMEM_BYTES);
    cudaFuncSetAttribute(sgemm_bf16, cudaFuncAttributeMaxDynamicSharedMemorySize, GEMM_SMEM_BYTES);

    dim3 gsX(Gq/128, MTOT/128);      // (32, 256)

    // ---- layer 1 ----
    cvt_bf16<<<(MTOT*Iq/4 + 255)/256, 256>>>(x, xb, MTOT*Iq/4);
    cvt_bf16<<<(Gq*Iq/4 + 255)/256, 256>>>(Wih0, wb, Gq*Iq/4);
    sgemm_bf16<<<gsX, 256, GEMM_SMEM_BYTES>>>(xb, wb, bih0, xproj, Iq, /*remap=*/1);
    // layer-1 hseq written as bf16 into xb (rows t*B+b) -> feeds layer-2 GEMM
    lstm_layer<<<NBLK, 256, LSTM_SMEM_BYTES>>>(xproj, Whh0, bhh0, xb);

    // ---- layer 2 ----
    cvt_bf16<<<(Gq*Hq/4 + 255)/256, 256>>>(Wih1, wb, Gq*Hq/4);
    sgemm_bf16<<<gsX, 256, GEMM_SMEM_BYTES>>>(xb, wb, bih1, xproj, Hq, /*remap=*/0);
    lstm_layer<<<NBLK, 256, LSTM_SMEM_BYTES>>>(xproj, Whh1, bhh1, hs2b);

    // ---- emissions + CRF ----
    emis_kernel<<<(MTOT*32)/256, 256>>>(hs2b, fcw, fcb, emis);
    crf_kernel<<<Bq, 32>>>(emis, labels, startt, endt, trans, llh);
    finalize_kernel<<<1, 64>>>(llh, (float*)d_out);
}